// round 14
// baseline (speedup 1.0000x reference)
#include <cuda_runtime.h>
#include <cuda_bf16.h>
#include <math.h>

#define H 512
#define W 512
#define B 32
#define CELL 16
#define NC 32            // cells per dim
#define NB 31            // blocks per dim
#define ORI 6
#define BLK_FEAT 24      // 2*2*ORI
#define HWsz (H*W)
#define NSTRIPS (B * NC) // 1024 jobs
#define GRID_A 592       // 148 SMs * 4 CTAs/SM target
#define NTASKS (NB * NB * 8)   // 7688 block-lane tasks per image

// scratch: per-cell histograms, (B, 32, 32, 6)
__device__ float g_cells[B * NC * NC * ORI];
// per-image strip-completion counters (zero-init; winner resets after use
// so every graph replay starts from 0)
__device__ unsigned int g_imgdone[B];

// single-instruction MUFU.SQRT (sqrt.approx.f32: 0 -> 0, ~1ulp on normals)
__device__ __forceinline__ float fast_sqrt(float v) {
    float r;
    asm("sqrt.approx.f32 %0, %1;" : "=f"(r) : "f"(v));
    return r;
}

// ---------------------------------------------------------------------------
// Phase 2: gradients + suffix-histogram accumulation (bit-exact sector tests).
// ---------------------------------------------------------------------------
template <bool BORDER>
__device__ __forceinline__ void phase2(
    const float (*sm)[512], int c, bool cok, int strip,
    float& S0, float& S1, float& S2, float& S3, float& S4, float& S5)
{
    const float C30 = 0.8660254037844386f;  // cos 30

    float w0 = sm[0][c];
    float w1 = sm[1][c];

    #pragma unroll
    for (int i = 0; i < 16; i++) {
        const float w2 = sm[i + 2][c];
        float gr = w2 - w0;
        if (BORDER) {
            const int r = strip * CELL + i;
            if (r == 0 || r == H - 1) gr = 0.0f;
        }
        const float gc = cok ? sm[i + 1][c + 1] - sm[i + 1][c - 1] : 0.0f;
        w0 = w1; w1 = w2;

        const float mag = fast_sqrt(gr * gr + gc * gc);

        float X = gc, Y = gr;
        if (Y < 0.0f || (Y == 0.0f && X < 0.0f)) { X = -X; Y = -Y; }

        const float a  = C30 * Y;
        const float b2 = 0.5f * X;
        const float cc = 0.5f * Y;
        const float d  = C30 * X;

        S0 += mag;
        S1 += ( a  >= b2  ) ? mag : 0.0f;        // angle >= 30
        S2 += ( cc >= d   ) ? mag : 0.0f;        // angle >= 60
        S3 += ( X  <= 0.0f) ? mag : 0.0f;        // angle >= 90
        S4 += (-cc >= d   ) ? mag : 0.0f;        // angle >= 120
        S5 += (-a  >= b2  ) ? mag : 0.0f;        // angle >= 150
    }
}

// ---------------------------------------------------------------------------
// Block normalization for one whole image (512 threads, 8 lanes per block).
// Identical math to the former kernel B.
// ---------------------------------------------------------------------------
__device__ void blocks_for_image(int b, const float* __restrict__ cells,
                                 float* __restrict__ out)
{
    const int tid = threadIdx.x;
    const float EPS2 = 1e-10f;  // (1e-5)^2

    // 16 uniform iterations; last one is ragged (guarded by 'act').
    #pragma unroll 1
    for (int k = 0; k < (NTASKS + 511) / 512; k++) {
        const int task = tid + k * 512;
        const bool act = (task < NTASKS);

        const int g = task >> 3;     // block index within image
        const int l = task & 7;      // lane within 8-group (aligned: 512%8==0)
        const int gi = act ? g : 0;
        const int i  = gi / NB;
        const int j  = gi - i * NB;

        const int row = i + (l >> 2);
        const int off = (l & 3) * 3;
        const float* p = cells + (((size_t)b * NC + row) * NC + j) * ORI + off;

        float v0 = 0.f, v1 = 0.f, v2 = 0.f;
        if (act) { v0 = p[0]; v1 = p[1]; v2 = p[2]; }

        float ss = v0 * v0 + v1 * v1 + v2 * v2;
        #pragma unroll
        for (int s = 4; s; s >>= 1) ss += __shfl_xor_sync(0xffffffffu, ss, s);
        const float inv_n1 = rsqrtf(ss + EPS2);
        v0 = fminf(v0 * inv_n1, 0.2f);
        v1 = fminf(v1 * inv_n1, 0.2f);
        v2 = fminf(v2 * inv_n1, 0.2f);

        float ss2 = v0 * v0 + v1 * v1 + v2 * v2;
        #pragma unroll
        for (int s = 4; s; s >>= 1) ss2 += __shfl_xor_sync(0xffffffffu, ss2, s);
        const float inv_n2 = rsqrtf(ss2 + EPS2);

        if (act) {
            float* o = out + ((size_t)b * NB * NB + g) * BLK_FEAT + l * 3;
            o[0] = v0 * inv_n2;
            o[1] = v1 * inv_n2;
            o[2] = v2 * inv_n2;
        }
    }
}

// ---------------------------------------------------------------------------
// Fused kernel: persistent strip CTAs (cells) + per-image block epilogue.
// The CTA whose strip completes an image runs that image's normalization.
// ---------------------------------------------------------------------------
__global__ __launch_bounds__(512) void hog_fused_kernel(
    const float* __restrict__ x, float* __restrict__ cells,
    float* __restrict__ out)
{
    __shared__ float sm[18][512];
    __shared__ int img_ready;

    const int tid = threadIdx.x;
    const int c = tid;              // column for phase 2
    const bool cok = (c > 0) && (c < W - 1);

    const int lrow_half = tid >> 8;          // 0 or 1
    const int col2 = (tid & 255);            // float2 slot in row
    const int colb = col2 << 1;              // float column

    for (int job = blockIdx.x; job < NSTRIPS; job += GRID_A) {
        const int strip = job & (NC - 1);   // cell row 0..31
        const int b     = job >> 5;         // image

        const float* xb = x + (size_t)b * 3 * HWsz;
        const int r0 = strip * CELL - 1;
        const bool border = (strip == 0) | (strip == NC - 1);

        __syncthreads();   // protect smem from previous iteration's readers

        if (!border) {
            #pragma unroll
            for (int it = 0; it < 9; it++) {
                const int i = 2 * it + lrow_half;      // local row 0..17
                const float2* base = (const float2*)(xb + (r0 + i) * W) + col2;
                const float2 R  = __ldg(base);
                const float2 G  = __ldg(base + (HWsz >> 1));
                const float2 Bc = __ldg(base + HWsz);
                float2 g;
                g.x = 0.299f * R.x + 0.587f * G.x + 0.114f * Bc.x;
                g.y = 0.299f * R.y + 0.587f * G.y + 0.114f * Bc.y;
                *((float2*)&sm[i][colb]) = g;
            }
        } else {
            #pragma unroll
            for (int it = 0; it < 9; it++) {
                const int i = 2 * it + lrow_half;
                const int r = r0 + i;
                float2 g = make_float2(0.f, 0.f);
                if (r >= 0 && r < H) {
                    const float2* base = (const float2*)(xb + r * W) + col2;
                    const float2 R  = __ldg(base);
                    const float2 G  = __ldg(base + (HWsz >> 1));
                    const float2 Bc = __ldg(base + HWsz);
                    g.x = 0.299f * R.x + 0.587f * G.x + 0.114f * Bc.x;
                    g.y = 0.299f * R.y + 0.587f * G.y + 0.114f * Bc.y;
                }
                *((float2*)&sm[i][colb]) = g;
            }
        }
        __syncthreads();

        float S0 = 0.f, S1 = 0.f, S2 = 0.f, S3 = 0.f, S4 = 0.f, S5 = 0.f;

        if (!border) phase2<false>(sm, c, cok, strip, S0, S1, S2, S3, S4, S5);
        else         phase2<true >(sm, c, cok, strip, S0, S1, S2, S3, S4, S5);

        #pragma unroll
        for (int s = 8; s; s >>= 1) {
            S0 += __shfl_xor_sync(0xffffffffu, S0, s);
            S1 += __shfl_xor_sync(0xffffffffu, S1, s);
            S2 += __shfl_xor_sync(0xffffffffu, S2, s);
            S3 += __shfl_xor_sync(0xffffffffu, S3, s);
            S4 += __shfl_xor_sync(0xffffffffu, S4, s);
            S5 += __shfl_xor_sync(0xffffffffu, S5, s);
        }

        if ((c & 15) == 0) {
            const int cellx = c >> 4;
            float* dst = cells + (((size_t)b * NC + strip) * NC + cellx) * ORI;
            const float inv = 1.0f / (CELL * CELL);
            dst[0] = (S0 - S1) * inv;
            dst[1] = (S1 - S2) * inv;
            dst[2] = (S2 - S3) * inv;
            dst[3] = (S3 - S4) * inv;
            dst[4] = (S4 - S5) * inv;
            // release: make this CTA's cell writes visible before counting
            __threadfence();
            dst[5] = S5 * inv;   // keep last store before fence? no -- move up
        }
        // NOTE: all 6 stores must precede the fence; redo ordering safely:
        if ((c & 15) == 0) {
            __threadfence();     // full fence after ALL stores above
        }
        __syncthreads();         // all writers have fenced

        if (tid == 0) {
            const unsigned old = atomicAdd(&g_imgdone[b], 1u);
            img_ready = (old == NC - 1);     // this CTA completed image b
            if (old == NC - 1) g_imgdone[b] = 0;  // reset for next replay
        }
        __syncthreads();

        if (img_ready) {
            __threadfence();     // acquire: see all CTAs' cell writes
            blocks_for_image(b, cells, out);
        }
    }
}

// ---------------------------------------------------------------------------
extern "C" void kernel_launch(void* const* d_in, const int* in_sizes, int n_in,
                              void* d_out, int out_size)
{
    const float* x = (const float*)d_in[0];
    float* out = (float*)d_out;

    float* cells;
    cudaGetSymbolAddress((void**)&cells, g_cells);

    hog_fused_kernel<<<GRID_A, 512>>>(x, cells, out);
}

// round 15
// speedup vs baseline: 1.6225x; 1.6225x over previous
#include <cuda_runtime.h>
#include <cuda_bf16.h>
#include <math.h>

#define H 512
#define W 512
#define B 32
#define CELL 16
#define NC 32            // cells per dim
#define NB 31            // blocks per dim
#define ORI 6
#define BLK_FEAT 24      // 2*2*ORI
#define HWsz (H*W)
#define NSTRIPS (B * NC) // 1024 jobs
#define GRID_A 592       // 148 SMs * 4 CTAs/SM (forced via launch_bounds)

// scratch: per-cell histograms, (B, 32, 32, 6)
__device__ float g_cells[B * NC * NC * ORI];

// single-instruction MUFU.SQRT (sqrt.approx.f32: 0 -> 0, ~1ulp on normals)
__device__ __forceinline__ float fast_sqrt(float v) {
    float r;
    asm("sqrt.approx.f32 %0, %1;" : "=f"(r) : "f"(v));
    return r;
}

// ---------------------------------------------------------------------------
// Phase 2: gradients + suffix-histogram accumulation. S_k = sum of mag where
// bin >= k; predicates are the 5 sector boundary tests as direct FSETP
// comparisons (bit-exact vs difference-then-compare).
// ---------------------------------------------------------------------------
template <bool BORDER>
__device__ __forceinline__ void phase2(
    const float (*sm)[512], int c, bool cok, int strip,
    float& S0, float& S1, float& S2, float& S3, float& S4, float& S5)
{
    const float C30 = 0.8660254037844386f;  // cos 30

    // rolling register window over own column: gr = sm[i+2][c] - sm[i][c]
    float w0 = sm[0][c];
    float w1 = sm[1][c];

    #pragma unroll
    for (int i = 0; i < 16; i++) {
        const float w2 = sm[i + 2][c];
        float gr = w2 - w0;
        if (BORDER) {
            const int r = strip * CELL + i;
            if (r == 0 || r == H - 1) gr = 0.0f;
        }
        const float gc = cok ? sm[i + 1][c + 1] - sm[i + 1][c - 1] : 0.0f;
        w0 = w1; w1 = w2;

        const float mag = fast_sqrt(gr * gr + gc * gc);

        // canonicalize to upper half-plane (angle mod 180 invariant)
        float X = gc, Y = gr;
        if (Y < 0.0f || (Y == 0.0f && X < 0.0f)) { X = -X; Y = -Y; }

        const float a  = C30 * Y;
        const float b2 = 0.5f * X;
        const float cc = 0.5f * Y;
        const float d  = C30 * X;

        S0 += mag;                               // always
        S1 += ( a  >= b2  ) ? mag : 0.0f;        // angle >= 30
        S2 += ( cc >= d   ) ? mag : 0.0f;        // angle >= 60
        S3 += ( X  <= 0.0f) ? mag : 0.0f;        // angle >= 90
        S4 += (-cc >= d   ) ? mag : 0.0f;        // angle >= 120
        S5 += (-a  >= b2  ) ? mag : 0.0f;        // angle >= 150
    }
}

// ---------------------------------------------------------------------------
// Kernel A: persistent strip CTAs, float2-vectorized load phase.
// __launch_bounds__(512, 4): cap regs at 32/thread so 4 CTAs/SM fit the
// 64K-reg file (measured 38 regs -> only 3 CTAs/SM, occ 66%).
// ---------------------------------------------------------------------------
__global__ __launch_bounds__(512, 4) void hog_cells_kernel(
    const float* __restrict__ x, float* __restrict__ cells)
{
    __shared__ float sm[18][512];
    const int tid = threadIdx.x;
    const int c = tid;              // column for phase 2
    const bool cok = (c > 0) && (c < W - 1);

    const int lrow_half = tid >> 8;          // 0 or 1
    const int col2 = (tid & 255);            // float2 slot in row
    const int colb = col2 << 1;              // float column

    for (int job = blockIdx.x; job < NSTRIPS; job += GRID_A) {
        const int strip = job & (NC - 1);   // cell row 0..31
        const int b     = job >> 5;         // image

        const float* xb = x + (size_t)b * 3 * HWsz;
        const int r0 = strip * CELL - 1;
        const bool border = (strip == 0) | (strip == NC - 1);

        __syncthreads();   // protect smem from previous iteration's readers

        if (!border) {
            #pragma unroll
            for (int it = 0; it < 9; it++) {
                const int i = 2 * it + lrow_half;      // local row 0..17
                const float2* base = (const float2*)(xb + (r0 + i) * W) + col2;
                const float2 R  = __ldg(base);
                const float2 G  = __ldg(base + (HWsz >> 1));
                const float2 Bc = __ldg(base + HWsz);
                float2 g;
                g.x = 0.299f * R.x + 0.587f * G.x + 0.114f * Bc.x;
                g.y = 0.299f * R.y + 0.587f * G.y + 0.114f * Bc.y;
                *((float2*)&sm[i][colb]) = g;
            }
        } else {
            #pragma unroll
            for (int it = 0; it < 9; it++) {
                const int i = 2 * it + lrow_half;
                const int r = r0 + i;
                float2 g = make_float2(0.f, 0.f);
                if (r >= 0 && r < H) {
                    const float2* base = (const float2*)(xb + r * W) + col2;
                    const float2 R  = __ldg(base);
                    const float2 G  = __ldg(base + (HWsz >> 1));
                    const float2 Bc = __ldg(base + HWsz);
                    g.x = 0.299f * R.x + 0.587f * G.x + 0.114f * Bc.x;
                    g.y = 0.299f * R.y + 0.587f * G.y + 0.114f * Bc.y;
                }
                *((float2*)&sm[i][colb]) = g;
            }
        }
        __syncthreads();

        float S0 = 0.f, S1 = 0.f, S2 = 0.f, S3 = 0.f, S4 = 0.f, S5 = 0.f;

        if (!border) phase2<false>(sm, c, cok, strip, S0, S1, S2, S3, S4, S5);
        else         phase2<true >(sm, c, cok, strip, S0, S1, S2, S3, S4, S5);

        // reduce suffix sums across the 16 lanes of each column group
        #pragma unroll
        for (int s = 8; s; s >>= 1) {
            S0 += __shfl_xor_sync(0xffffffffu, S0, s);
            S1 += __shfl_xor_sync(0xffffffffu, S1, s);
            S2 += __shfl_xor_sync(0xffffffffu, S2, s);
            S3 += __shfl_xor_sync(0xffffffffu, S3, s);
            S4 += __shfl_xor_sync(0xffffffffu, S4, s);
            S5 += __shfl_xor_sync(0xffffffffu, S5, s);
        }

        if ((c & 15) == 0) {
            const int cellx = c >> 4;
            float* dst = cells + (((size_t)b * NC + strip) * NC + cellx) * ORI;
            const float inv = 1.0f / (CELL * CELL);
            dst[0] = (S0 - S1) * inv;
            dst[1] = (S1 - S2) * inv;
            dst[2] = (S2 - S3) * inv;
            dst[3] = (S3 - S4) * inv;
            dst[4] = (S4 - S5) * inv;
            dst[5] = S5 * inv;
        }
    }

#if __CUDA_ARCH__ >= 900
    cudaTriggerProgrammaticLaunchCompletion();
#endif
}

// ---------------------------------------------------------------------------
// Kernel B: 8 lanes per HOG block; rsqrt-based L2-Hys. PDL-launched so its
// ramp overlaps kernel A's tail.
// ---------------------------------------------------------------------------
__global__ __launch_bounds__(256) void hog_blocks_kernel(
    const float* __restrict__ cells, float* __restrict__ out)
{
#if __CUDA_ARCH__ >= 900
    cudaGridDependencySynchronize();
#endif

    const int t = blockIdx.x * blockDim.x + threadIdx.x;
    const int g = t >> 3;           // HOG block index
    const int l = t & 7;            // lane within group
    const int total = B * NB * NB;
    if (g >= total) return;

    const int b  = g / (NB * NB);
    const int ij = g - b * (NB * NB);
    const int i  = ij / NB;
    const int j  = ij - i * NB;

    const int row = i + (l >> 2);
    const int off = (l & 3) * 3;
    const float* p = cells + (((size_t)b * NC + row) * NC + j) * ORI + off;

    float v0 = __ldg(p);
    float v1 = __ldg(p + 1);
    float v2 = __ldg(p + 2);

    const float EPS2 = 1e-10f;  // (1e-5)^2

    float ss = v0 * v0 + v1 * v1 + v2 * v2;
    #pragma unroll
    for (int s = 4; s; s >>= 1) ss += __shfl_xor_sync(0xffffffffu, ss, s);
    const float inv_n1 = rsqrtf(ss + EPS2);
    v0 = fminf(v0 * inv_n1, 0.2f);
    v1 = fminf(v1 * inv_n1, 0.2f);
    v2 = fminf(v2 * inv_n1, 0.2f);

    float ss2 = v0 * v0 + v1 * v1 + v2 * v2;
    #pragma unroll
    for (int s = 4; s; s >>= 1) ss2 += __shfl_xor_sync(0xffffffffu, ss2, s);
    const float inv_n2 = rsqrtf(ss2 + EPS2);

    float* o = out + (size_t)g * BLK_FEAT + l * 3;
    o[0] = v0 * inv_n2;
    o[1] = v1 * inv_n2;
    o[2] = v2 * inv_n2;
}

// ---------------------------------------------------------------------------
extern "C" void kernel_launch(void* const* d_in, const int* in_sizes, int n_in,
                              void* d_out, int out_size)
{
    const float* x = (const float*)d_in[0];
    float* out = (float*)d_out;

    float* cells;
    cudaGetSymbolAddress((void**)&cells, g_cells);

    hog_cells_kernel<<<GRID_A, 512>>>(x, cells);

    const int total = B * NB * NB;                 // 30752
    const int threadsB = total * 8;

    cudaLaunchConfig_t cfg = {};
    cfg.gridDim  = dim3((threadsB + 255) / 256);
    cfg.blockDim = dim3(256);
    cfg.dynamicSmemBytes = 0;
    cfg.stream = 0;
    cudaLaunchAttribute attrs[1];
    attrs[0].id = cudaLaunchAttributeProgrammaticStreamSerialization;
    attrs[0].val.programmaticStreamSerializationAllowed = 1;
    cfg.attrs = attrs;
    cfg.numAttrs = 1;
    cudaLaunchKernelEx(&cfg, hog_blocks_kernel, (const float*)cells, out);
}